// round 6
// baseline (speedup 1.0000x reference)
#include <cuda_runtime.h>
#include <cuda_bf16.h>

#define N_NODES 50000
#define N_EDGES 800000
#define IN_DIM  128
#define HID     64
#define N_GRAPHS 64
#define MAXDEG  64   // P(Poisson(16) > 64) ~ 1e-17 per node; safe

// ---------------- device scratch ----------------
__device__ float g_g[N_NODES * HID];      // dinv-scaled linear output (message payload)
__device__ float g_a[N_NODES * HID];      // activation between layers
__device__ int   g_deg[N_NODES];
__device__ int   g_adj[N_NODES * MAXDEG]; // bucket adjacency: sources per target
__device__ int   g_batch[N_NODES];
__device__ float g_pool[N_GRAPHS * HID];
__device__ int   g_cnt[N_GRAPHS];
__device__ int   g_is64;

// ---------------- init (+ fused index-dtype detection in block 0) ----------------
__global__ void k_init(const int* __restrict__ ei32) {
    int i = blockIdx.x * blockDim.x + threadIdx.x;
    int stride = gridDim.x * blockDim.x;
    if (blockIdx.x == 0) {
        __shared__ int any;
        if (threadIdx.x == 0) any = 0;
        __syncthreads();
        int v = 0;
        for (int j = threadIdx.x; j < 1024; j += blockDim.x) v |= ei32[2 * j + 1];
        if (v) atomicOr(&any, 1);
        __syncthreads();
        if (threadIdx.x == 0) g_is64 = (any == 0) ? 1 : 0;
    }
    for (int j = i; j < N_NODES; j += stride) g_deg[j] = 0;
    if (i < N_GRAPHS * HID) g_pool[i] = 0.f;
    if (i < N_GRAPHS) g_cnt[i] = 0;
}

// ---------------- prep: convert + bucket-fill adjacency + batch (2 edges/thread) ----------------
__global__ void k_prep(const void* __restrict__ ei, const void* __restrict__ batch) {
    int i = blockIdx.x * blockDim.x + threadIdx.x;
    int is64 = g_is64;
    const int HALF = N_EDGES / 2;
    if (i < HALF) {
        int r0, c0, r1, c1;
        if (is64) {
            const long long* p = (const long long*)ei;
            r0 = (int)p[i];           c0 = (int)p[N_EDGES + i];
            r1 = (int)p[i + HALF];    c1 = (int)p[N_EDGES + i + HALF];
        } else {
            const int* p = (const int*)ei;
            r0 = p[i];                c0 = p[N_EDGES + i];
            r1 = p[i + HALF];         c1 = p[N_EDGES + i + HALF];
        }
        int p0 = atomicAdd(&g_deg[c0], 1);
        int p1 = atomicAdd(&g_deg[c1], 1);
        if (p0 < MAXDEG) g_adj[c0 * MAXDEG + p0] = r0;
        if (p1 < MAXDEG) g_adj[c1 * MAXDEG + p1] = r1;
    }
    if (i < N_NODES) {
        int b = is64 ? (int)((const long long*)batch)[i] : ((const int*)batch)[i];
        g_batch[i] = b;
        atomicAdd(&g_cnt[b], 1);
    }
}

// ---------------- GEMM: g_g[n,f] = rsqrt(deg[n]+1) * sum_k X[n,k] * W[k,f] ----------------
// Block: 256 threads = 32 nodes x 8 threads; each thread produces 8 floats (2 float4).
template<int K, bool FROM_A>
__global__ void k_gemm(const float* __restrict__ Xin, const float* __restrict__ W) {
    __shared__ float sW[K * HID];
    __shared__ float sx[32 * K];
    const float* X = FROM_A ? (const float*)g_a : Xin;
    int t = threadIdx.x;
    int n0 = blockIdx.x * 32;
    for (int j = t; j < K * HID; j += 256) sW[j] = W[j];
    for (int j = t; j < 32 * K; j += 256) {
        int idx = n0 * K + j;
        sx[j] = (idx < N_NODES * K) ? X[idx] : 0.f;
    }
    __syncthreads();
    int node = t >> 3, q2 = (t & 7) * 2;   // two float4 slots: q2, q2+1
    int n = n0 + node;
    const float* xr = &sx[node * K];
    const float4* w4 = (const float4*)sW;
    float4 A = make_float4(0.f, 0.f, 0.f, 0.f);
    float4 B = make_float4(0.f, 0.f, 0.f, 0.f);
    #pragma unroll 8
    for (int k = 0; k < K; k++) {
        float xv = xr[k];
        float4 wa = w4[k * 16 + q2];
        float4 wb = w4[k * 16 + q2 + 1];
        A.x += xv * wa.x; A.y += xv * wa.y; A.z += xv * wa.z; A.w += xv * wa.w;
        B.x += xv * wb.x; B.y += xv * wb.y; B.z += xv * wb.z; B.w += xv * wb.w;
    }
    if (n < N_NODES) {
        float d = rsqrtf((float)(g_deg[n] + 1));
        float4* dst = ((float4*)g_g) + n * 16 + q2;
        dst[0] = make_float4(A.x * d, A.y * d, A.z * d, A.w * d);
        dst[1] = make_float4(B.x * d, B.y * d, B.z * d, B.w * d);
    }
}

// ---------------- gather over one 32-edge region; indices live in areg (register) ----------------
__device__ __forceinline__ float4 gather_region(const float4* __restrict__ G4, int fq, int half,
                                                int areg, int len, float4 acc) {
    int i = 0;
    for (; i + 8 <= len; i += 8) {
        int e0 = __shfl_sync(0xFFFFFFFFu, areg, i + 0 + half);
        int e1 = __shfl_sync(0xFFFFFFFFu, areg, i + 2 + half);
        int e2 = __shfl_sync(0xFFFFFFFFu, areg, i + 4 + half);
        int e3 = __shfl_sync(0xFFFFFFFFu, areg, i + 6 + half);
        float4 v0 = G4[e0 * 16 + fq];
        float4 v1 = G4[e1 * 16 + fq];
        float4 v2 = G4[e2 * 16 + fq];
        float4 v3 = G4[e3 * 16 + fq];
        acc.x += (v0.x + v1.x) + (v2.x + v3.x);
        acc.y += (v0.y + v1.y) + (v2.y + v3.y);
        acc.z += (v0.z + v1.z) + (v2.z + v3.z);
        acc.w += (v0.w + v1.w) + (v2.w + v3.w);
    }
    for (; i + 2 <= len; i += 2) {
        int e = __shfl_sync(0xFFFFFFFFu, areg, i + half);
        float4 v = G4[e * 16 + fq];
        acc.x += v.x; acc.y += v.y; acc.z += v.z; acc.w += v.w;
    }
    if (i < len) {                       // odd tail: half 0 only
        int e = __shfl_sync(0xFFFFFFFFu, areg, i);
        if (half == 0) {
            float4 v = G4[e * 16 + fq];
            acc.x += v.x; acc.y += v.y; acc.z += v.z; acc.w += v.w;
        }
    }
    return acc;
}

// Full neighborhood sum incl. self-loop; valid on all lanes after the xor-combine.
__device__ __forceinline__ float4 gather_sum4(int node, int lane, int d) {
    int half = lane >> 4;
    int fq   = lane & 15;
    const float4* G4 = (const float4*)g_g;
    const int* adj = &g_adj[node * MAXDEG];
    d = min(d, MAXDEG);
    int a0 = (lane < d)      ? adj[lane]      : 0;   // coalesced: 1 LDG per warp
    int a1 = (32 + lane < d) ? adj[32 + lane] : 0;
    float4 acc = make_float4(0.f, 0.f, 0.f, 0.f);
    if (half == 0) acc = G4[node * 16 + fq];         // self-loop counted once
    int d0 = min(d, 32);
    acc = gather_region(G4, fq, half, a0, d0, acc);
    if (d > 32) acc = gather_region(G4, fq, half, a1, d - 32, acc);
    acc.x += __shfl_xor_sync(0xFFFFFFFFu, acc.x, 16);
    acc.y += __shfl_xor_sync(0xFFFFFFFFu, acc.y, 16);
    acc.z += __shfl_xor_sync(0xFFFFFFFFu, acc.z, 16);
    acc.w += __shfl_xor_sync(0xFFFFFFFFu, acc.w, 16);
    return acc;
}

// ---------------- agg1: gather + relu -> g_a ----------------
__global__ void k_agg1(const float* __restrict__ b) {
    int warp = (blockIdx.x * blockDim.x + threadIdx.x) >> 5;
    if (warp >= N_NODES) return;
    int lane = threadIdx.x & 31;
    int d = g_deg[warp];
    float4 acc = gather_sum4(warp, lane, d);
    if (lane < 16) {
        float dc = rsqrtf((float)(d + 1));
        float4 bb = ((const float4*)b)[lane];
        float4 o;
        o.x = fmaxf(acc.x * dc + bb.x, 0.f);
        o.y = fmaxf(acc.y * dc + bb.y, 0.f);
        o.z = fmaxf(acc.z * dc + bb.z, 0.f);
        o.w = fmaxf(acc.w * dc + bb.w, 0.f);
        ((float4*)g_a)[warp * 16 + lane] = o;
    }
}

// ---------------- agg2: gather + relu, RED straight into pool ----------------
__global__ void k_agg2(const float* __restrict__ b) {
    int warp = (blockIdx.x * blockDim.x + threadIdx.x) >> 5;
    if (warp >= N_NODES) return;
    int lane = threadIdx.x & 31;
    int d = g_deg[warp];
    float4 acc = gather_sum4(warp, lane, d);
    if (lane < 16) {
        float dc = rsqrtf((float)(d + 1));
        float4 bb = ((const float4*)b)[lane];
        float ox = fmaxf(acc.x * dc + bb.x, 0.f);
        float oy = fmaxf(acc.y * dc + bb.y, 0.f);
        float oz = fmaxf(acc.z * dc + bb.z, 0.f);
        float ow = fmaxf(acc.w * dc + bb.w, 0.f);
        int gid = g_batch[warp];
        float* dst = &g_pool[gid * HID + lane * 4];
        asm volatile("red.global.add.v4.f32 [%0], {%1,%2,%3,%4};"
                     :: "l"(dst), "f"(ox), "f"(oy), "f"(oz), "f"(ow) : "memory");
    }
}

// ---------------- final: mean, linear [64,2], log_softmax ----------------
__global__ void k_final(const float* __restrict__ Wl, const float* __restrict__ bl,
                        float* __restrict__ out) {
    int gph = threadIdx.x;
    if (gph >= N_GRAPHS) return;
    float cnt = fmaxf((float)g_cnt[gph], 1.f);
    float inv = 1.f / cnt;
    float l0 = bl[0], l1 = bl[1];
    #pragma unroll
    for (int k = 0; k < HID; k++) {
        float p = g_pool[gph * HID + k] * inv;
        l0 += p * Wl[k * 2 + 0];
        l1 += p * Wl[k * 2 + 1];
    }
    float m = fmaxf(l0, l1);
    float lse = m + logf(expf(l0 - m) + expf(l1 - m));
    out[gph * 2 + 0] = l0 - lse;
    out[gph * 2 + 1] = l1 - lse;
}

extern "C" void kernel_launch(void* const* d_in, const int* in_sizes, int n_in,
                              void* d_out, int out_size) {
    const float* x  = (const float*)d_in[0];
    const void*  ei = d_in[1];
    const void*  bt = d_in[2];
    const float* W1 = (const float*)d_in[3];
    const float* b1 = (const float*)d_in[4];
    const float* W2 = (const float*)d_in[5];
    const float* b2 = (const float*)d_in[6];
    const float* Wl = (const float*)d_in[7];
    const float* bl = (const float*)d_in[8];
    float* out = (float*)d_out;

    k_init<<<256, 256>>>((const int*)ei);
    k_prep<<<(N_EDGES / 2 + 255) / 256, 256>>>(ei, bt);

    // conv1
    k_gemm<IN_DIM, false><<<(N_NODES + 31) / 32, 256>>>(x, W1);
    k_agg1<<<(N_NODES * 32 + 255) / 256, 256>>>(b1);

    // conv2
    k_gemm<HID, true><<<(N_NODES + 31) / 32, 256>>>(nullptr, W2);
    k_agg2<<<(N_NODES * 32 + 255) / 256, 256>>>(b2);

    // head
    k_final<<<1, 64>>>(Wl, bl, out);
}

// round 7
// speedup vs baseline: 1.3245x; 1.3245x over previous
#include <cuda_runtime.h>
#include <cuda_bf16.h>

#define N_NODES 50000
#define N_EDGES 800000
#define IN_DIM  128
#define HID     64
#define N_GRAPHS 64
#define MAXDEG  64   // P(Poisson(16) > 64) ~ 1e-17 per node; safe

// ---------------- device scratch ----------------
__device__ float g_g[N_NODES * HID];      // conv1 payload: dinv * (x @ W1)
__device__ float g_a[N_NODES * HID];      // conv2 payload: dinv * (relu(conv1) @ W2)
__device__ int   g_deg[N_NODES];
__device__ int   g_adj[N_NODES * MAXDEG]; // bucket adjacency: sources per target
__device__ int   g_batch[N_NODES];
__device__ float g_pool[N_GRAPHS * HID];
__device__ int   g_cnt[N_GRAPHS];
__device__ int   g_is64;

// ---------------- init (+ fused index-dtype detection in block 0) ----------------
__global__ void k_init(const int* __restrict__ ei32) {
    int i = blockIdx.x * blockDim.x + threadIdx.x;
    int stride = gridDim.x * blockDim.x;
    if (blockIdx.x == 0) {
        __shared__ int any;
        if (threadIdx.x == 0) any = 0;
        __syncthreads();
        int v = 0;
        for (int j = threadIdx.x; j < 1024; j += blockDim.x) v |= ei32[2 * j + 1];
        if (v) atomicOr(&any, 1);
        __syncthreads();
        if (threadIdx.x == 0) g_is64 = (any == 0) ? 1 : 0;
    }
    for (int j = i; j < N_NODES; j += stride) g_deg[j] = 0;
    if (i < N_GRAPHS * HID) g_pool[i] = 0.f;
    if (i < N_GRAPHS) g_cnt[i] = 0;
}

// ---------------- prep: convert + bucket-fill adjacency + batch (2 edges/thread) ----------------
__global__ void k_prep(const void* __restrict__ ei, const void* __restrict__ batch) {
    int i = blockIdx.x * blockDim.x + threadIdx.x;
    int is64 = g_is64;
    const int HALF = N_EDGES / 2;
    if (i < HALF) {
        int r0, c0, r1, c1;
        if (is64) {
            const long long* p = (const long long*)ei;
            r0 = (int)p[i];           c0 = (int)p[N_EDGES + i];
            r1 = (int)p[i + HALF];    c1 = (int)p[N_EDGES + i + HALF];
        } else {
            const int* p = (const int*)ei;
            r0 = p[i];                c0 = p[N_EDGES + i];
            r1 = p[i + HALF];         c1 = p[N_EDGES + i + HALF];
        }
        int p0 = atomicAdd(&g_deg[c0], 1);
        int p1 = atomicAdd(&g_deg[c1], 1);
        if (p0 < MAXDEG) g_adj[c0 * MAXDEG + p0] = r0;
        if (p1 < MAXDEG) g_adj[c1 * MAXDEG + p1] = r1;
    }
    if (i < N_NODES) {
        int b = is64 ? (int)((const long long*)batch)[i] : ((const int*)batch)[i];
        g_batch[i] = b;
        atomicAdd(&g_cnt[b], 1);
    }
}

// ---------------- GEMM1 (R5-proven shape): 16 nodes x 16 float4-slots per block ----------------
__global__ void k_gemm1(const float* __restrict__ X, const float* __restrict__ W) {
    const int K = IN_DIM;
    __shared__ float sW[K * HID];
    __shared__ float sx[16 * K];
    int t = threadIdx.x;
    int n0 = blockIdx.x * 16;
    for (int j = t; j < K * HID; j += 256) sW[j] = W[j];
    for (int j = t; j < 16 * K; j += 256) {
        int idx = n0 * K + j;
        sx[j] = (idx < N_NODES * K) ? X[idx] : 0.f;
    }
    __syncthreads();
    int node = t >> 4, q = t & 15;
    int n = n0 + node;
    const float* xr = &sx[node * K];
    const float4* w4 = (const float4*)sW;
    float ax = 0.f, ay = 0.f, az = 0.f, aw = 0.f;
    #pragma unroll 8
    for (int k = 0; k < K; k++) {
        float xv = xr[k];
        float4 w = w4[k * 16 + q];
        ax += xv * w.x; ay += xv * w.y; az += xv * w.z; aw += xv * w.w;
    }
    if (n < N_NODES) {
        float d = rsqrtf((float)(g_deg[n] + 1));
        ((float4*)g_g)[n * 16 + q] = make_float4(ax * d, ay * d, az * d, aw * d);
    }
}

// ---------------- gather over one 32-edge region; indices in register, shfl-distributed ----------------
__device__ __forceinline__ float4 gather_region(const float4* __restrict__ G4, int fq, int half,
                                                int areg, int len, float4 acc) {
    int i = 0;
    for (; i + 8 <= len; i += 8) {
        int e0 = __shfl_sync(0xFFFFFFFFu, areg, i + 0 + half);
        int e1 = __shfl_sync(0xFFFFFFFFu, areg, i + 2 + half);
        int e2 = __shfl_sync(0xFFFFFFFFu, areg, i + 4 + half);
        int e3 = __shfl_sync(0xFFFFFFFFu, areg, i + 6 + half);
        float4 v0 = G4[e0 * 16 + fq];
        float4 v1 = G4[e1 * 16 + fq];
        float4 v2 = G4[e2 * 16 + fq];
        float4 v3 = G4[e3 * 16 + fq];
        acc.x += (v0.x + v1.x) + (v2.x + v3.x);
        acc.y += (v0.y + v1.y) + (v2.y + v3.y);
        acc.z += (v0.z + v1.z) + (v2.z + v3.z);
        acc.w += (v0.w + v1.w) + (v2.w + v3.w);
    }
    for (; i + 2 <= len; i += 2) {
        int e = __shfl_sync(0xFFFFFFFFu, areg, i + half);
        float4 v = G4[e * 16 + fq];
        acc.x += v.x; acc.y += v.y; acc.z += v.z; acc.w += v.w;
    }
    if (i < len) {
        int e = __shfl_sync(0xFFFFFFFFu, areg, i);
        if (half == 0) {
            float4 v = G4[e * 16 + fq];
            acc.x += v.x; acc.y += v.y; acc.z += v.z; acc.w += v.w;
        }
    }
    return acc;
}

// Full neighborhood sum incl. self-loop over payload P; valid on all lanes after combine.
__device__ __forceinline__ float4 gather_sum4(const float* __restrict__ P,
                                              int node, int lane, int d) {
    int half = lane >> 4;
    int fq   = lane & 15;
    const float4* G4 = (const float4*)P;
    const int* adj = &g_adj[node * MAXDEG];
    int a0 = (lane < d)      ? adj[lane]      : 0;   // coalesced: 1 LDG per warp
    int a1 = (32 + lane < d) ? adj[32 + lane] : 0;
    float4 acc = make_float4(0.f, 0.f, 0.f, 0.f);
    if (half == 0) acc = G4[node * 16 + fq];         // self-loop counted once
    int d0 = min(d, 32);
    acc = gather_region(G4, fq, half, a0, d0, acc);
    if (d > 32) acc = gather_region(G4, fq, half, a1, d - 32, acc);
    acc.x += __shfl_xor_sync(0xFFFFFFFFu, acc.x, 16);
    acc.y += __shfl_xor_sync(0xFFFFFFFFu, acc.y, 16);
    acc.z += __shfl_xor_sync(0xFFFFFFFFu, acc.z, 16);
    acc.w += __shfl_xor_sync(0xFFFFFFFFu, acc.w, 16);
    return acc;
}

// ---------------- agg1 fused with gemm2:
// o[n,:] = relu(dinv*(gather)+b1); g_a[n,f] = dinv * sum_k o[n,k]*W2[k,f] ----------------
__global__ void k_agg1g2(const float* __restrict__ b1, const float* __restrict__ W2) {
    __shared__ float sW2[HID * HID];   // 16 KB
    for (int j = threadIdx.x; j < HID * HID; j += blockDim.x) sW2[j] = W2[j];
    __syncthreads();

    int warp = (blockIdx.x * blockDim.x + threadIdx.x) >> 5;
    if (warp >= N_NODES) return;
    int lane = threadIdx.x & 31;
    int d = min(g_deg[warp], MAXDEG);
    float4 acc = gather_sum4(g_g, warp, lane, d);

    float dc = rsqrtf((float)(d + 1));
    int fq = lane & 15;
    float4 bb = ((const float4*)b1)[fq];
    float4 o;                                   // activation, all lanes (dup halves)
    o.x = fmaxf(acc.x * dc + bb.x, 0.f);
    o.y = fmaxf(acc.y * dc + bb.y, 0.f);
    o.z = fmaxf(acc.z * dc + bb.z, 0.f);
    o.w = fmaxf(acc.w * dc + bb.w, 0.f);

    // in-warp GEMM: each lane computes output features f0=2*lane, f0+1
    int f0 = lane * 2;
    float s0 = 0.f, s1 = 0.f;
    const float2* W2r = (const float2*)sW2;     // [k][HID/2] float2
    #pragma unroll
    for (int r = 0; r < 16; r++) {              // broadcast features 4r..4r+3 from lane r
        float a0 = __shfl_sync(0xFFFFFFFFu, o.x, r);
        float a1 = __shfl_sync(0xFFFFFFFFu, o.y, r);
        float a2 = __shfl_sync(0xFFFFFFFFu, o.z, r);
        float a3 = __shfl_sync(0xFFFFFFFFu, o.w, r);
        float2 w0 = W2r[(4 * r + 0) * 32 + lane];
        float2 w1 = W2r[(4 * r + 1) * 32 + lane];
        float2 w2 = W2r[(4 * r + 2) * 32 + lane];
        float2 w3 = W2r[(4 * r + 3) * 32 + lane];
        s0 += a0 * w0.x + a1 * w1.x + a2 * w2.x + a3 * w3.x;
        s1 += a0 * w0.y + a1 * w1.y + a2 * w2.y + a3 * w3.y;
    }
    ((float2*)g_a)[warp * 32 + lane] = make_float2(s0 * dc, s1 * dc);
}

// ---------------- agg2: gather over g_a + relu, RED straight into pool ----------------
__global__ void k_agg2(const float* __restrict__ b) {
    int warp = (blockIdx.x * blockDim.x + threadIdx.x) >> 5;
    if (warp >= N_NODES) return;
    int lane = threadIdx.x & 31;
    int d = min(g_deg[warp], MAXDEG);
    float4 acc = gather_sum4(g_a, warp, lane, d);
    if (lane < 16) {
        float dc = rsqrtf((float)(d + 1));
        float4 bb = ((const float4*)b)[lane];
        float ox = fmaxf(acc.x * dc + bb.x, 0.f);
        float oy = fmaxf(acc.y * dc + bb.y, 0.f);
        float oz = fmaxf(acc.z * dc + bb.z, 0.f);
        float ow = fmaxf(acc.w * dc + bb.w, 0.f);
        int gid = g_batch[warp];
        float* dst = &g_pool[gid * HID + lane * 4];
        asm volatile("red.global.add.v4.f32 [%0], {%1,%2,%3,%4};"
                     :: "l"(dst), "f"(ox), "f"(oy), "f"(oz), "f"(ow) : "memory");
    }
}

// ---------------- final: mean, linear [64,2], log_softmax ----------------
__global__ void k_final(const float* __restrict__ Wl, const float* __restrict__ bl,
                        float* __restrict__ out) {
    int gph = threadIdx.x;
    if (gph >= N_GRAPHS) return;
    float cnt = fmaxf((float)g_cnt[gph], 1.f);
    float inv = 1.f / cnt;
    float l0 = bl[0], l1 = bl[1];
    #pragma unroll
    for (int k = 0; k < HID; k++) {
        float p = g_pool[gph * HID + k] * inv;
        l0 += p * Wl[k * 2 + 0];
        l1 += p * Wl[k * 2 + 1];
    }
    float m = fmaxf(l0, l1);
    float lse = m + logf(expf(l0 - m) + expf(l1 - m));
    out[gph * 2 + 0] = l0 - lse;
    out[gph * 2 + 1] = l1 - lse;
}

extern "C" void kernel_launch(void* const* d_in, const int* in_sizes, int n_in,
                              void* d_out, int out_size) {
    const float* x  = (const float*)d_in[0];
    const void*  ei = d_in[1];
    const void*  bt = d_in[2];
    const float* W1 = (const float*)d_in[3];
    const float* b1 = (const float*)d_in[4];
    const float* W2 = (const float*)d_in[5];
    const float* b2 = (const float*)d_in[6];
    const float* Wl = (const float*)d_in[7];
    const float* bl = (const float*)d_in[8];
    float* out = (float*)d_out;

    k_init<<<256, 256>>>((const int*)ei);
    k_prep<<<(N_EDGES / 2 + 255) / 256, 256>>>(ei, bt);

    // conv1 linear
    k_gemm1<<<(N_NODES + 15) / 16, 256>>>(x, W1);
    // conv1 aggregate + relu + conv2 linear (fused)
    k_agg1g2<<<(N_NODES * 32 + 255) / 256, 256>>>(b1, W2);
    // conv2 aggregate + relu + pool
    k_agg2<<<(N_NODES * 32 + 255) / 256, 256>>>(b2);

    // head
    k_final<<<1, 64>>>(Wl, bl, out);
}

// round 8
// speedup vs baseline: 1.8431x; 1.3916x over previous
#include <cuda_runtime.h>
#include <cuda_bf16.h>

#define N_NODES 50000
#define N_EDGES 800000
#define IN_DIM  128
#define HID     64
#define N_GRAPHS 64
#define MAXDEG  64   // P(Poisson(16) > 64) ~ 1e-17 per node; safe

// ---------------- device scratch ----------------
__device__ float g_g[N_NODES * HID];      // GEMM output payload (both layers)
__device__ float g_a[N_NODES * HID];      // conv1 activation
__device__ int   g_deg[N_NODES];
__device__ int   g_adj[N_NODES * MAXDEG]; // bucket adjacency: sources per target
__device__ int   g_batch[N_NODES];
__device__ float g_pool[N_GRAPHS * HID];
__device__ int   g_cnt[N_GRAPHS];
__device__ int   g_is64;

// ---------------- init (+ fused index-dtype detection in block 0) ----------------
__global__ void k_init(const int* __restrict__ ei32) {
    int i = blockIdx.x * blockDim.x + threadIdx.x;
    int stride = gridDim.x * blockDim.x;
    if (blockIdx.x == 0) {
        __shared__ int any;
        if (threadIdx.x == 0) any = 0;
        __syncthreads();
        int v = 0;
        for (int j = threadIdx.x; j < 1024; j += blockDim.x) v |= ei32[2 * j + 1];
        if (v) atomicOr(&any, 1);
        __syncthreads();
        if (threadIdx.x == 0) g_is64 = (any == 0) ? 1 : 0;
    }
    for (int j = i; j < N_NODES; j += stride) g_deg[j] = 0;
    if (i < N_GRAPHS * HID) g_pool[i] = 0.f;
    if (i < N_GRAPHS) g_cnt[i] = 0;
}

// ---------------- prep: convert + bucket-fill adjacency + batch (2 edges/thread) ----------------
__global__ void k_prep(const void* __restrict__ ei, const void* __restrict__ batch) {
    int i = blockIdx.x * blockDim.x + threadIdx.x;
    int is64 = g_is64;
    const int HALF = N_EDGES / 2;
    if (i < HALF) {
        int r0, c0, r1, c1;
        if (is64) {
            const long long* p = (const long long*)ei;
            r0 = (int)p[i];           c0 = (int)p[N_EDGES + i];
            r1 = (int)p[i + HALF];    c1 = (int)p[N_EDGES + i + HALF];
        } else {
            const int* p = (const int*)ei;
            r0 = p[i];                c0 = p[N_EDGES + i];
            r1 = p[i + HALF];         c1 = p[N_EDGES + i + HALF];
        }
        int p0 = atomicAdd(&g_deg[c0], 1);
        int p1 = atomicAdd(&g_deg[c1], 1);
        if (p0 < MAXDEG) g_adj[c0 * MAXDEG + p0] = r0;
        if (p1 < MAXDEG) g_adj[c1 * MAXDEG + p1] = r1;
    }
    if (i < N_NODES) {
        int b = is64 ? (int)((const long long*)batch)[i] : ((const int*)batch)[i];
        g_batch[i] = b;
        atomicAdd(&g_cnt[b], 1);
    }
}

// ---------------- register-tiled GEMM: OUT[n,f] = rsqrt(deg+1) * sum_k X[n,k] W[k,f] ----
// Block tile: 128 nodes x 64 feats; K chunked by 32 (x transposed in smem).
// Thread (tx 0..15 = feature quad, ty 0..15 = node octet): 8 nodes x 4 feats in regs,
// accumulated as packed f32x2 pairs.
#define GK  32     // K chunk
#define GNT 128    // node tile
#define GNP 132    // padded stride for sxT rows

#define SPLAT2(dst, s) asm("mov.b64 %0, {%1,%1};" : "=l"(dst) : "r"(__float_as_uint(s)))
#define FMA2(acc, a, b) asm("fma.rn.f32x2 %0, %1, %2, %0;" : "+l"(acc) : "l"(a), "l"(b))

template<int K, bool FROM_A>
__global__ void k_gemm(const float* __restrict__ Xin, const float* __restrict__ W) {
    __shared__ float sxT[GK][GNP];    // 16.9 KB
    __shared__ float sW[GK * HID];    // 8 KB
    const float* X = FROM_A ? (const float*)g_a : Xin;
    int t = threadIdx.x;
    int n0 = blockIdx.x * GNT;
    int tx = t & 15;          // feature quad: feats 4tx..4tx+3
    int ty = t >> 4;          // node octet: nodes ty*8..ty*8+7
    int ty8 = ty * 8;

    unsigned long long accA[8], accB[8];
    #pragma unroll
    for (int i = 0; i < 8; i++) { accA[i] = 0ULL; accB[i] = 0ULL; }

    for (int kc = 0; kc < K; kc += GK) {
        // W chunk: GK x 64 floats = 512 float4, 2 per thread
        {
            const float4* Wg = (const float4*)(W + kc * HID);
            float4* sW4 = (float4*)sW;
            sW4[t]       = Wg[t];
            sW4[t + 256] = Wg[t + 256];
        }
        // X chunk transposed: 128 nodes x 32 k = 1024 float4 reads, 4 per thread
        #pragma unroll
        for (int j = t; j < 1024; j += 256) {
            int node = j >> 3;
            int k4 = (j & 7) * 4;
            int gn = n0 + node;
            float4 v = (gn < N_NODES) ? ((const float4*)(X + gn * K + kc))[j & 7]
                                      : make_float4(0.f, 0.f, 0.f, 0.f);
            sxT[k4 + 0][node] = v.x;
            sxT[k4 + 1][node] = v.y;
            sxT[k4 + 2][node] = v.z;
            sxT[k4 + 3][node] = v.w;
        }
        __syncthreads();
        const float4* sW4 = (const float4*)sW;
        #pragma unroll 8
        for (int k = 0; k < GK; k++) {
            float4 w = sW4[k * 16 + tx];
            unsigned long long w01, w23;
            asm("mov.b64 %0, {%1,%2};" : "=l"(w01) : "f"(w.x), "f"(w.y));
            asm("mov.b64 %0, {%1,%2};" : "=l"(w23) : "f"(w.z), "f"(w.w));
            float4 xa = *(const float4*)(&sxT[k][ty8]);
            float4 xb = *(const float4*)(&sxT[k][ty8 + 4]);
            unsigned long long xx;
            SPLAT2(xx, xa.x); FMA2(accA[0], w01, xx); FMA2(accB[0], w23, xx);
            SPLAT2(xx, xa.y); FMA2(accA[1], w01, xx); FMA2(accB[1], w23, xx);
            SPLAT2(xx, xa.z); FMA2(accA[2], w01, xx); FMA2(accB[2], w23, xx);
            SPLAT2(xx, xa.w); FMA2(accA[3], w01, xx); FMA2(accB[3], w23, xx);
            SPLAT2(xx, xb.x); FMA2(accA[4], w01, xx); FMA2(accB[4], w23, xx);
            SPLAT2(xx, xb.y); FMA2(accA[5], w01, xx); FMA2(accB[5], w23, xx);
            SPLAT2(xx, xb.z); FMA2(accA[6], w01, xx); FMA2(accB[6], w23, xx);
            SPLAT2(xx, xb.w); FMA2(accA[7], w01, xx); FMA2(accB[7], w23, xx);
        }
        __syncthreads();
    }

    #pragma unroll
    for (int i = 0; i < 8; i++) {
        int n = n0 + ty8 + i;
        if (n < N_NODES) {
            float dc = rsqrtf((float)(g_deg[n] + 1));
            float f0, f1, f2, f3;
            asm("mov.b64 {%0,%1}, %2;" : "=f"(f0), "=f"(f1) : "l"(accA[i]));
            asm("mov.b64 {%0,%1}, %2;" : "=f"(f2), "=f"(f3) : "l"(accB[i]));
            ((float4*)g_g)[n * 16 + tx] = make_float4(f0 * dc, f1 * dc, f2 * dc, f3 * dc);
        }
    }
}

// ---------------- gather over one 32-edge region; indices in register, shfl-distributed ----------------
__device__ __forceinline__ float4 gather_region(const float4* __restrict__ G4, int fq, int half,
                                                int areg, int len, float4 acc) {
    int i = 0;
    for (; i + 8 <= len; i += 8) {
        int e0 = __shfl_sync(0xFFFFFFFFu, areg, i + 0 + half);
        int e1 = __shfl_sync(0xFFFFFFFFu, areg, i + 2 + half);
        int e2 = __shfl_sync(0xFFFFFFFFu, areg, i + 4 + half);
        int e3 = __shfl_sync(0xFFFFFFFFu, areg, i + 6 + half);
        float4 v0 = G4[e0 * 16 + fq];
        float4 v1 = G4[e1 * 16 + fq];
        float4 v2 = G4[e2 * 16 + fq];
        float4 v3 = G4[e3 * 16 + fq];
        acc.x += (v0.x + v1.x) + (v2.x + v3.x);
        acc.y += (v0.y + v1.y) + (v2.y + v3.y);
        acc.z += (v0.z + v1.z) + (v2.z + v3.z);
        acc.w += (v0.w + v1.w) + (v2.w + v3.w);
    }
    for (; i + 2 <= len; i += 2) {
        int e = __shfl_sync(0xFFFFFFFFu, areg, i + half);
        float4 v = G4[e * 16 + fq];
        acc.x += v.x; acc.y += v.y; acc.z += v.z; acc.w += v.w;
    }
    if (i < len) {
        int e = __shfl_sync(0xFFFFFFFFu, areg, i);
        if (half == 0) {
            float4 v = G4[e * 16 + fq];
            acc.x += v.x; acc.y += v.y; acc.z += v.z; acc.w += v.w;
        }
    }
    return acc;
}

// Full neighborhood sum incl. self-loop over g_g; valid on all lanes after combine.
__device__ __forceinline__ float4 gather_sum4(int node, int lane, int d) {
    int half = lane >> 4;
    int fq   = lane & 15;
    const float4* G4 = (const float4*)g_g;
    const int* adj = &g_adj[node * MAXDEG];
    int a0 = (lane < d)      ? adj[lane]      : 0;   // coalesced: 1 LDG per warp
    int a1 = (32 + lane < d) ? adj[32 + lane] : 0;
    float4 acc = make_float4(0.f, 0.f, 0.f, 0.f);
    if (half == 0) acc = G4[node * 16 + fq];         // self-loop counted once
    int d0 = min(d, 32);
    acc = gather_region(G4, fq, half, a0, d0, acc);
    if (d > 32) acc = gather_region(G4, fq, half, a1, d - 32, acc);
    acc.x += __shfl_xor_sync(0xFFFFFFFFu, acc.x, 16);
    acc.y += __shfl_xor_sync(0xFFFFFFFFu, acc.y, 16);
    acc.z += __shfl_xor_sync(0xFFFFFFFFu, acc.z, 16);
    acc.w += __shfl_xor_sync(0xFFFFFFFFu, acc.w, 16);
    return acc;
}

// ---------------- agg1: gather over g_g + relu -> g_a ----------------
__global__ void k_agg1(const float* __restrict__ b) {
    int warp = (blockIdx.x * blockDim.x + threadIdx.x) >> 5;
    if (warp >= N_NODES) return;
    int lane = threadIdx.x & 31;
    int d = min(g_deg[warp], MAXDEG);
    float4 acc = gather_sum4(warp, lane, d);
    if (lane < 16) {
        float dc = rsqrtf((float)(d + 1));
        float4 bb = ((const float4*)b)[lane];
        float4 o;
        o.x = fmaxf(acc.x * dc + bb.x, 0.f);
        o.y = fmaxf(acc.y * dc + bb.y, 0.f);
        o.z = fmaxf(acc.z * dc + bb.z, 0.f);
        o.w = fmaxf(acc.w * dc + bb.w, 0.f);
        ((float4*)g_a)[warp * 16 + lane] = o;
    }
}

// ---------------- agg2: gather over g_g + relu, RED straight into pool ----------------
__global__ void k_agg2(const float* __restrict__ b) {
    int warp = (blockIdx.x * blockDim.x + threadIdx.x) >> 5;
    if (warp >= N_NODES) return;
    int lane = threadIdx.x & 31;
    int d = min(g_deg[warp], MAXDEG);
    float4 acc = gather_sum4(warp, lane, d);
    if (lane < 16) {
        float dc = rsqrtf((float)(d + 1));
        float4 bb = ((const float4*)b)[lane];
        float ox = fmaxf(acc.x * dc + bb.x, 0.f);
        float oy = fmaxf(acc.y * dc + bb.y, 0.f);
        float oz = fmaxf(acc.z * dc + bb.z, 0.f);
        float ow = fmaxf(acc.w * dc + bb.w, 0.f);
        int gid = g_batch[warp];
        float* dst = &g_pool[gid * HID + lane * 4];
        asm volatile("red.global.add.v4.f32 [%0], {%1,%2,%3,%4};"
                     :: "l"(dst), "f"(ox), "f"(oy), "f"(oz), "f"(ow) : "memory");
    }
}

// ---------------- final: mean, linear [64,2], log_softmax ----------------
__global__ void k_final(const float* __restrict__ Wl, const float* __restrict__ bl,
                        float* __restrict__ out) {
    int gph = threadIdx.x;
    if (gph >= N_GRAPHS) return;
    float cnt = fmaxf((float)g_cnt[gph], 1.f);
    float inv = 1.f / cnt;
    float l0 = bl[0], l1 = bl[1];
    #pragma unroll
    for (int k = 0; k < HID; k++) {
        float p = g_pool[gph * HID + k] * inv;
        l0 += p * Wl[k * 2 + 0];
        l1 += p * Wl[k * 2 + 1];
    }
    float m = fmaxf(l0, l1);
    float lse = m + logf(expf(l0 - m) + expf(l1 - m));
    out[gph * 2 + 0] = l0 - lse;
    out[gph * 2 + 1] = l1 - lse;
}

extern "C" void kernel_launch(void* const* d_in, const int* in_sizes, int n_in,
                              void* d_out, int out_size) {
    const float* x  = (const float*)d_in[0];
    const void*  ei = d_in[1];
    const void*  bt = d_in[2];
    const float* W1 = (const float*)d_in[3];
    const float* b1 = (const float*)d_in[4];
    const float* W2 = (const float*)d_in[5];
    const float* b2 = (const float*)d_in[6];
    const float* Wl = (const float*)d_in[7];
    const float* bl = (const float*)d_in[8];
    float* out = (float*)d_out;

    const int GB = (N_NODES + GNT - 1) / GNT;   // 391

    k_init<<<256, 256>>>((const int*)ei);
    k_prep<<<(N_EDGES / 2 + 255) / 256, 256>>>(ei, bt);

    // conv1: linear (x @ W1, pre-scaled), aggregate + relu
    k_gemm<IN_DIM, false><<<GB, 256>>>(x, W1);
    k_agg1<<<(N_NODES * 32 + 255) / 256, 256>>>(b1);

    // conv2: linear (a @ W2, pre-scaled) into g_g, aggregate + relu + pool
    k_gemm<HID, true><<<GB, 256>>>(nullptr, W2);
    k_agg2<<<(N_NODES * 32 + 255) / 256, 256>>>(b2);

    // head
    k_final<<<1, 64>>>(Wl, bl, out);
}